// round 1
// baseline (speedup 1.0000x reference)
#include <cuda_runtime.h>
#include <math.h>

#define Bb 16
#define Tt 256
#define Ee 512
#define Hh 1024
#define Vv 32000
#define G3 3072
#define Mm (Bb*Tt)   // 4096

// ---- scratch (static device arrays; no allocation in kernel_launch) ----
__device__ float g_gi[(size_t)Mm*G3];   // [M, 3H]  gi = x@W_ih^T + b_ih
__device__ float g_hs[(size_t)Mm*Hh];   // [M, H]   all hidden states (m = b*T+t)
__device__ float g_y [(size_t)Mm*Hh];   // [M, H]   relu(lin1)
__device__ float g_lse[Mm];             // per-row logsumexp

// ============================================================
// Generic tiled SGEMM: C[m,n] = act( sum_k Arow(m)[k]*B[n*K+k] + bias[n] )
// Arow(m) = gidx ? A + gidx[m]*K : A + m*K
// BM=BN=128, BK=8, 256 threads, 8x8 microtile. M%128==0, N%128==0, K%8==0.
// ============================================================
__global__ void sgemm_kernel(const float* __restrict__ A,
                             const float* __restrict__ Bm,
                             const float* __restrict__ bias,
                             float* __restrict__ C,
                             int M, int N, int K,
                             const int* __restrict__ gidx,
                             int do_relu)
{
    __shared__ float As[8][128];
    __shared__ float Bs[8][128];

    const int tid = threadIdx.x;
    const int bn  = blockIdx.x;
    const int bm  = blockIdx.y;

    // loader assignment: each thread owns one row (of 128) and half the k-slab
    const int lrow = tid >> 1;          // 0..127
    const int kq   = (tid & 1) * 4;     // 0 or 4

    const int arow_g = bm * 128 + lrow;
    const float* Ap = gidx ? (A + (size_t)gidx[arow_g] * K)
                           : (A + (size_t)arow_g * K);
    const float* Bp = Bm + (size_t)(bn * 128 + lrow) * K;

    // compute assignment
    const int tx = tid & 15;            // 0..15
    const int ty = tid >> 4;            // 0..15
    const int m0 = ty * 8;
    const int n0 = tx * 8;

    float acc[8][8];
#pragma unroll
    for (int i = 0; i < 8; i++)
#pragma unroll
        for (int j = 0; j < 8; j++) acc[i][j] = 0.f;

    for (int kt = 0; kt < K; kt += 8) {
        float4 av = *(const float4*)(Ap + kt + kq);
        float4 bv = *(const float4*)(Bp + kt + kq);
        As[kq+0][lrow] = av.x; As[kq+1][lrow] = av.y;
        As[kq+2][lrow] = av.z; As[kq+3][lrow] = av.w;
        Bs[kq+0][lrow] = bv.x; Bs[kq+1][lrow] = bv.y;
        Bs[kq+2][lrow] = bv.z; Bs[kq+3][lrow] = bv.w;
        __syncthreads();

#pragma unroll
        for (int kk = 0; kk < 8; kk++) {
            float4 a0 = *(const float4*)&As[kk][m0];
            float4 a1 = *(const float4*)&As[kk][m0 + 4];
            float4 b0 = *(const float4*)&Bs[kk][n0];
            float4 b1 = *(const float4*)&Bs[kk][n0 + 4];
            float am[8] = {a0.x,a0.y,a0.z,a0.w,a1.x,a1.y,a1.z,a1.w};
            float bb[8] = {b0.x,b0.y,b0.z,b0.w,b1.x,b1.y,b1.z,b1.w};
#pragma unroll
            for (int i = 0; i < 8; i++)
#pragma unroll
                for (int j = 0; j < 8; j++)
                    acc[i][j] = fmaf(am[i], bb[j], acc[i][j]);
        }
        __syncthreads();
    }

    // epilogue
    const int ncol0 = bn * 128 + n0;
    float bsv[8];
#pragma unroll
    for (int j = 0; j < 8; j++) bsv[j] = bias[ncol0 + j];

#pragma unroll
    for (int i = 0; i < 8; i++) {
        const int m = bm * 128 + m0 + i;
        float* crow = C + (size_t)m * N + ncol0;
#pragma unroll
        for (int jq = 0; jq < 2; jq++) {
            float4 v;
            v.x = acc[i][jq*4+0] + bsv[jq*4+0];
            v.y = acc[i][jq*4+1] + bsv[jq*4+1];
            v.z = acc[i][jq*4+2] + bsv[jq*4+2];
            v.w = acc[i][jq*4+3] + bsv[jq*4+3];
            if (do_relu) {
                v.x = fmaxf(v.x, 0.f); v.y = fmaxf(v.y, 0.f);
                v.z = fmaxf(v.z, 0.f); v.w = fmaxf(v.w, 0.f);
            }
            *(float4*)(crow + jq*4) = v;
        }
    }
}

// ============================================================
// GRU step t: h_t = (1-z)*n + z*h_{t-1}
// grid = 128 blocks, 256 thr (8 warps). Block handles j-chunk of 8 (warp/j),
// all 16 batches. h_{t-1} staged in 64KB dynamic smem.
// gh = h_{t-1} @ W_hh^T ; gates combined with precomputed g_gi.
// ============================================================
__global__ void gru_step_kernel(const float* __restrict__ W_hh,
                                const float* __restrict__ b_hh,
                                int t)
{
    extern __shared__ float h_s[];   // [16][1024]
    const int tid = threadIdx.x;

    if (t == 0) {
        for (int i = tid; i < Bb*Hh/4; i += 256)
            ((float4*)h_s)[i] = make_float4(0.f,0.f,0.f,0.f);
    } else {
        for (int i = tid*4; i < Bb*Hh; i += 256*4) {
            int b = i >> 10;          // /H
            int k = i & (Hh-1);
            *(float4*)&h_s[i] = *(const float4*)&g_hs[((size_t)(b*Tt + t - 1))*Hh + k];
        }
    }
    __syncthreads();

    const int w    = tid >> 5;
    const int lane = tid & 31;
    const int j    = blockIdx.x * 8 + w;          // 0..1023

    const float* wr = W_hh + (size_t)j            * Hh;
    const float* wz = W_hh + (size_t)(j + Hh)     * Hh;
    const float* wn = W_hh + (size_t)(j + 2*Hh)   * Hh;

    float ar[16], az[16], an[16];
#pragma unroll
    for (int b = 0; b < 16; b++) { ar[b] = 0.f; az[b] = 0.f; an[b] = 0.f; }

    for (int i = 0; i < 32; i++) {
        const int k = i*32 + lane;
        const float vr = wr[k];
        const float vz = wz[k];
        const float vn = wn[k];
#pragma unroll
        for (int b = 0; b < 16; b++) {
            const float hv = h_s[b*Hh + k];
            ar[b] = fmaf(vr, hv, ar[b]);
            az[b] = fmaf(vz, hv, az[b]);
            an[b] = fmaf(vn, hv, an[b]);
        }
    }

    // warp butterfly reduction (result replicated to all lanes)
#pragma unroll
    for (int b = 0; b < 16; b++) {
#pragma unroll
        for (int o = 16; o > 0; o >>= 1) {
            ar[b] += __shfl_xor_sync(0xffffffffu, ar[b], o);
            az[b] += __shfl_xor_sync(0xffffffffu, az[b], o);
            an[b] += __shfl_xor_sync(0xffffffffu, an[b], o);
        }
    }

    if (lane < 16) {
        const int b = lane;
        const float* gi = g_gi + ((size_t)(b*Tt + t)) * G3;
        const float ir  = gi[j];
        const float iz  = gi[j + Hh];
        const float inn = gi[j + 2*Hh];
        const float r = 1.f / (1.f + expf(-(ir + ar[b] + b_hh[j])));
        const float z = 1.f / (1.f + expf(-(iz + az[b] + b_hh[j + Hh])));
        const float n = tanhf(inn + r * (an[b] + b_hh[j + 2*Hh]));
        const float hp = h_s[b*Hh + j];
        g_hs[((size_t)(b*Tt + t))*Hh + j] = (1.f - z)*n + z*hp;
    }
}

// ============================================================
// log-softmax: pass 1 per-row online logsumexp, pass 2 subtract
// ============================================================
__global__ void lse_kernel(const float* __restrict__ logits)
{
    const int row = blockIdx.x;
    const float* x = logits + (size_t)row * Vv;
    float m = -INFINITY, s = 0.f;
    for (int v = threadIdx.x; v < Vv; v += 256) {
        const float xv = x[v];
        if (xv > m) { s = s * expf(m - xv) + 1.f; m = xv; }
        else        { s += expf(xv - m); }
    }
    __shared__ float sm[256], ss[256];
    sm[threadIdx.x] = m; ss[threadIdx.x] = s;
    __syncthreads();
    for (int o = 128; o > 0; o >>= 1) {
        if (threadIdx.x < o) {
            const float m2 = sm[threadIdx.x + o], s2 = ss[threadIdx.x + o];
            const float M_ = fmaxf(sm[threadIdx.x], m2);
            ss[threadIdx.x] = ss[threadIdx.x]*expf(sm[threadIdx.x]-M_) + s2*expf(m2-M_);
            sm[threadIdx.x] = M_;
        }
        __syncthreads();
    }
    if (threadIdx.x == 0) g_lse[row] = sm[0] + logf(ss[0]);
}

__global__ void sub_kernel(float* __restrict__ out)
{
    const size_t i = (size_t)blockIdx.x * blockDim.x + threadIdx.x; // float4 idx
    const size_t n4 = (size_t)Mm * Vv / 4;
    if (i >= n4) return;
    const int row = (int)((i * 4) / Vv);
    const float l = g_lse[row];
    float4 v = ((float4*)out)[i];
    v.x -= l; v.y -= l; v.z -= l; v.w -= l;
    ((float4*)out)[i] = v;
}

__global__ void hidden_copy_kernel(float* __restrict__ out)
{
    const int i = blockIdx.x * blockDim.x + threadIdx.x;   // 0..16383
    const int b = i >> 10;
    const int j = i & (Hh - 1);
    out[(size_t)Mm*Vv + i] = g_hs[((size_t)(b*Tt + Tt - 1))*Hh + j];
}

// ============================================================
extern "C" void kernel_launch(void* const* d_in, const int* in_sizes, int n_in,
                              void* d_out, int out_size)
{
    const int*   inputs = (const int*)  d_in[0];
    const float* emb    = (const float*)d_in[1];
    const float* W_ih   = (const float*)d_in[2];
    const float* W_hh   = (const float*)d_in[3];
    const float* b_ih   = (const float*)d_in[4];
    const float* b_hh   = (const float*)d_in[5];
    const float* W1     = (const float*)d_in[6];
    const float* b1     = (const float*)d_in[7];
    const float* W2     = (const float*)d_in[8];
    const float* b2     = (const float*)d_in[9];
    float* out = (float*)d_out;

    float *p_gi, *p_hs, *p_y;
    cudaGetSymbolAddress((void**)&p_gi, g_gi);
    cudaGetSymbolAddress((void**)&p_hs, g_hs);
    cudaGetSymbolAddress((void**)&p_y,  g_y);

    cudaFuncSetAttribute(gru_step_kernel,
                         cudaFuncAttributeMaxDynamicSharedMemorySize, Bb*Hh*4);

    // 1) gi = gather(emb, inputs) @ W_ih^T + b_ih    [4096 x 3072], K=512
    {
        dim3 grid(G3/128, Mm/128);
        sgemm_kernel<<<grid, 256>>>(emb, W_ih, b_ih, p_gi,
                                    Mm, G3, Ee, inputs, 0);
    }

    // 2) GRU scan: 256 sequential steps
    for (int t = 0; t < Tt; t++) {
        gru_step_kernel<<<128, 256, Bb*Hh*4>>>(W_hh, b_hh, t);
    }

    // 3) y = relu(hs @ W1^T + b1)    [4096 x 1024], K=1024
    {
        dim3 grid(Hh/128, Mm/128);
        sgemm_kernel<<<grid, 256>>>(p_hs, W1, b1, p_y,
                                    Mm, Hh, Hh, nullptr, 1);
    }

    // 4) logits = y @ W2^T + b2 -> write into d_out   [4096 x 32000], K=1024
    {
        dim3 grid(Vv/128, Mm/128);
        sgemm_kernel<<<grid, 256>>>(p_y, W2, b2, out,
                                    Mm, Vv, Hh, nullptr, 0);
    }

    // 5) log_softmax in place
    lse_kernel<<<Mm, 256>>>(out);
    {
        const size_t n4 = (size_t)Mm * Vv / 4;
        const int blocks = (int)((n4 + 255) / 256);
        sub_kernel<<<blocks, 256>>>(out);
    }

    // 6) hidden = h_{T-1}
    hidden_copy_kernel<<<(Bb*Hh)/256, 256>>>(out);
}

// round 3
// speedup vs baseline: 1.9354x; 1.9354x over previous
#include <cuda_runtime.h>
#include <cuda_bf16.h>
#include <math.h>
#include <cstdint>

#define Bb 16
#define Tt 256
#define Ee 512
#define Hh 1024
#define Vv 32000
#define G3 3072
#define Mm (Bb*Tt)   // 4096

// ---- scratch ----
__device__ float g_gi[(size_t)Mm*G3];
__device__ float g_hs[(size_t)Mm*Hh];
__device__ float g_y [(size_t)Mm*Hh];
__device__ float g_lse[Mm];
__device__ __nv_bfloat16 g_W1b[(size_t)Hh*Hh];
__device__ __nv_bfloat16 g_W2b[(size_t)Vv*Hh];
__device__ __nv_bfloat16 g_hsb[(size_t)Mm*Hh];
__device__ __nv_bfloat16 g_yb [(size_t)Mm*Hh];

__device__ __forceinline__ uint32_t smem_u32(const void* p) {
    uint32_t a;
    asm("{ .reg .u64 t; cvta.to.shared.u64 t, %1; cvt.u32.u64 %0, t; }" : "=r"(a) : "l"(p));
    return a;
}

// ================= fp32 -> bf16 =================
__global__ void f2bf_kernel(const float* __restrict__ x, __nv_bfloat16* __restrict__ o, int n4)
{
    int i = blockIdx.x * blockDim.x + threadIdx.x;
    if (i >= n4) return;
    float4 v = ((const float4*)x)[i];
    __nv_bfloat162* p = (__nv_bfloat162*)o + i * 2;
    p[0] = __floats2bfloat162_rn(v.x, v.y);
    p[1] = __floats2bfloat162_rn(v.z, v.w);
}

// ================= HMMA bf16 GEMM: C = A @ B^T + bias =================
// A [M,K] bf16 row-major, B [N,K] bf16 row-major, C [M,N] fp32.
// Block tile 128x128, BK=32, 256 threads = 8 warps (4 m x 2 n), warp tile 32x64.
// smem rows: 32 bf16 data padded to stride 40 bf16 (80 B) -> ldmatrix conflict-free.
#define HG_STRIDE  40                       // bf16 elems per smem row
#define HG_ATILE   (128 * HG_STRIDE * 2)    // 10240 B
#define HG_STAGE   (2 * HG_ATILE)           // A + B = 20480 B
#define HG_SMEM    (2 * HG_STAGE)           // double buffered = 40960 B

__device__ __forceinline__ void ldsm_x4(uint32_t* r, uint32_t addr) {
    asm volatile("ldmatrix.sync.aligned.m8n8.x4.shared.b16 {%0,%1,%2,%3}, [%4];"
                 : "=r"(r[0]), "=r"(r[1]), "=r"(r[2]), "=r"(r[3]) : "r"(addr));
}
__device__ __forceinline__ void mma16816(float* d, const uint32_t* a, uint32_t b0, uint32_t b1) {
    asm volatile("mma.sync.aligned.m16n8k16.row.col.f32.bf16.bf16.f32 "
                 "{%0,%1,%2,%3}, {%4,%5,%6,%7}, {%8,%9}, {%0,%1,%2,%3};"
                 : "+f"(d[0]), "+f"(d[1]), "+f"(d[2]), "+f"(d[3])
                 : "r"(a[0]), "r"(a[1]), "r"(a[2]), "r"(a[3]), "r"(b0), "r"(b1));
}
__device__ __forceinline__ void cp_async16(uint32_t saddr, const void* gaddr) {
    asm volatile("cp.async.cg.shared.global [%0], [%1], 16;" :: "r"(saddr), "l"(gaddr));
}

__global__ void __launch_bounds__(256) hmma_gemm_kernel(
    const __nv_bfloat16* __restrict__ A,
    const __nv_bfloat16* __restrict__ Bm,
    const float* __restrict__ bias,
    float* __restrict__ C,
    int M, int N, int K, int do_relu)
{
    extern __shared__ char smem[];
    const uint32_t sb = smem_u32(smem);
    const int tid  = threadIdx.x;
    const int wid  = tid >> 5;
    const int lane = tid & 31;
    const int bn = blockIdx.x, bm = blockIdx.y;

    const int warp_m = wid & 3;        // 0..3 -> 32 rows each
    const int warp_n = wid >> 2;       // 0..1 -> 64 cols each

    // loader: 2 A-chunks + 2 B-chunks of 16B per thread per stage
    const int l_row = tid >> 1;                 // shared by the two chunks? no:
    // idx = tid*? use: for s in 0..1: idx = tid + s*256 -> row=idx>>2, c=idx&3

    float d[2][8][4];
#pragma unroll
    for (int i = 0; i < 2; i++)
#pragma unroll
        for (int j = 0; j < 8; j++)
#pragma unroll
            for (int q = 0; q < 4; q++) d[i][j][q] = 0.f;

    const int NK = K >> 5;     // BK=32

    // ldmatrix lane addressing (constant per thread)
    const int lmat = lane >> 3;       // 0..3
    const int lrow = lane & 7;        // 0..7

    auto load_stage = [&](int it, int buf) {
        const int kt = it << 5;
        const uint32_t sa = sb + buf * HG_STAGE;
        const uint32_t sbB = sa + HG_ATILE;
#pragma unroll
        for (int s = 0; s < 2; s++) {
            const int idx = tid + s * 256;
            const int row = idx >> 2, c = idx & 3;
            cp_async16(sa + row * (HG_STRIDE*2) + c * 16,
                       A + (size_t)(bm * 128 + row) * K + kt + c * 8);
            cp_async16(sbB + row * (HG_STRIDE*2) + c * 16,
                       Bm + (size_t)(bn * 128 + row) * K + kt + c * 8);
        }
        asm volatile("cp.async.commit_group;");
    };

    load_stage(0, 0);

    for (int it = 0; it < NK; it++) {
        if (it + 1 < NK) {
            load_stage(it + 1, (it + 1) & 1);
            asm volatile("cp.async.wait_group 1;");
        } else {
            asm volatile("cp.async.wait_group 0;");
        }
        __syncthreads();

        const uint32_t sa  = sb + (it & 1) * HG_STAGE;
        const uint32_t sbB = sa + HG_ATILE;

#pragma unroll
        for (int ks = 0; ks < 2; ks++) {
            uint32_t a[2][4];
#pragma unroll
            for (int mt = 0; mt < 2; mt++) {
                const int row = warp_m * 32 + mt * 16 + (lmat & 1) * 8 + lrow;
                const int c   = ks * 2 + (lmat >> 1);
                ldsm_x4(a[mt], sa + row * (HG_STRIDE*2) + c * 16);
            }
            uint32_t b[4][4];
#pragma unroll
            for (int nt = 0; nt < 4; nt++) {
                const int n = warp_n * 64 + nt * 16 + (lmat >> 1) * 8 + lrow;
                const int c = ks * 2 + (lmat & 1);
                ldsm_x4(b[nt], sbB + n * (HG_STRIDE*2) + c * 16);
            }
#pragma unroll
            for (int mt = 0; mt < 2; mt++)
#pragma unroll
                for (int nt = 0; nt < 4; nt++) {
                    mma16816(d[mt][nt*2+0], a[mt], b[nt][0], b[nt][1]);
                    mma16816(d[mt][nt*2+1], a[mt], b[nt][2], b[nt][3]);
                }
        }
        __syncthreads();
    }

    // epilogue
#pragma unroll
    for (int mt = 0; mt < 2; mt++) {
        const int row0 = bm * 128 + warp_m * 32 + mt * 16 + (lane >> 2);
#pragma unroll
        for (int nt8 = 0; nt8 < 8; nt8++) {
            const int col = bn * 128 + warp_n * 64 + nt8 * 8 + (lane & 3) * 2;
            const float b0 = bias[col], b1 = bias[col + 1];
            float2 v0, v1;
            v0.x = d[mt][nt8][0] + b0; v0.y = d[mt][nt8][1] + b1;
            v1.x = d[mt][nt8][2] + b0; v1.y = d[mt][nt8][3] + b1;
            if (do_relu) {
                v0.x = fmaxf(v0.x, 0.f); v0.y = fmaxf(v0.y, 0.f);
                v1.x = fmaxf(v1.x, 0.f); v1.y = fmaxf(v1.y, 0.f);
            }
            *(float2*)(C + (size_t)row0 * N + col)       = v0;
            *(float2*)(C + (size_t)(row0 + 8) * N + col) = v1;
        }
    }
}

// ================= fp32 SIMT SGEMM (gi, gathered A) =================
__global__ void sgemm_kernel(const float* __restrict__ A,
                             const float* __restrict__ Bm,
                             const float* __restrict__ bias,
                             float* __restrict__ C,
                             int M, int N, int K,
                             const int* __restrict__ gidx,
                             int do_relu)
{
    __shared__ float As[8][128];
    __shared__ float Bs[8][128];

    const int tid = threadIdx.x;
    const int bn  = blockIdx.x;
    const int bm  = blockIdx.y;

    const int lrow = tid >> 1;
    const int kq   = (tid & 1) * 4;

    const int arow_g = bm * 128 + lrow;
    const float* Ap = gidx ? (A + (size_t)gidx[arow_g] * K)
                           : (A + (size_t)arow_g * K);
    const float* Bp = Bm + (size_t)(bn * 128 + lrow) * K;

    const int tx = tid & 15;
    const int ty = tid >> 4;
    const int m0 = ty * 8;
    const int n0 = tx * 8;

    float acc[8][8];
#pragma unroll
    for (int i = 0; i < 8; i++)
#pragma unroll
        for (int j = 0; j < 8; j++) acc[i][j] = 0.f;

    for (int kt = 0; kt < K; kt += 8) {
        float4 av = *(const float4*)(Ap + kt + kq);
        float4 bv = *(const float4*)(Bp + kt + kq);
        As[kq+0][lrow] = av.x; As[kq+1][lrow] = av.y;
        As[kq+2][lrow] = av.z; As[kq+3][lrow] = av.w;
        Bs[kq+0][lrow] = bv.x; Bs[kq+1][lrow] = bv.y;
        Bs[kq+2][lrow] = bv.z; Bs[kq+3][lrow] = bv.w;
        __syncthreads();

#pragma unroll
        for (int kk = 0; kk < 8; kk++) {
            float4 a0 = *(const float4*)&As[kk][m0];
            float4 a1 = *(const float4*)&As[kk][m0 + 4];
            float4 b0 = *(const float4*)&Bs[kk][n0];
            float4 b1 = *(const float4*)&Bs[kk][n0 + 4];
            float am[8] = {a0.x,a0.y,a0.z,a0.w,a1.x,a1.y,a1.z,a1.w};
            float bb[8] = {b0.x,b0.y,b0.z,b0.w,b1.x,b1.y,b1.z,b1.w};
#pragma unroll
            for (int i = 0; i < 8; i++)
#pragma unroll
                for (int j = 0; j < 8; j++)
                    acc[i][j] = fmaf(am[i], bb[j], acc[i][j]);
        }
        __syncthreads();
    }

    const int ncol0 = bn * 128 + n0;
    float bsv[8];
#pragma unroll
    for (int j = 0; j < 8; j++) bsv[j] = bias[ncol0 + j];

#pragma unroll
    for (int i = 0; i < 8; i++) {
        const int m = bm * 128 + m0 + i;
        float* crow = C + (size_t)m * N + ncol0;
#pragma unroll
        for (int jq = 0; jq < 2; jq++) {
            float4 v;
            v.x = acc[i][jq*4+0] + bsv[jq*4+0];
            v.y = acc[i][jq*4+1] + bsv[jq*4+1];
            v.z = acc[i][jq*4+2] + bsv[jq*4+2];
            v.w = acc[i][jq*4+3] + bsv[jq*4+3];
            if (do_relu) {
                v.x = fmaxf(v.x, 0.f); v.y = fmaxf(v.y, 0.f);
                v.z = fmaxf(v.z, 0.f); v.w = fmaxf(v.w, 0.f);
            }
            *(float4*)(crow + jq*4) = v;
        }
    }
}

// ================= GRU step =================
__global__ void gru_step_kernel(const float* __restrict__ W_hh,
                                const float* __restrict__ b_hh,
                                int t)
{
    extern __shared__ float h_s[];   // [16][1024]
    const int tid = threadIdx.x;

    if (t == 0) {
        for (int i = tid; i < Bb*Hh/4; i += 256)
            ((float4*)h_s)[i] = make_float4(0.f,0.f,0.f,0.f);
    } else {
        for (int i = tid*4; i < Bb*Hh; i += 256*4) {
            int b = i >> 10;
            int k = i & (Hh-1);
            *(float4*)&h_s[i] = *(const float4*)&g_hs[((size_t)(b*Tt + t - 1))*Hh + k];
        }
    }
    __syncthreads();

    const int w    = tid >> 5;
    const int lane = tid & 31;
    const int j    = blockIdx.x * 8 + w;

    const float* wr = W_hh + (size_t)j            * Hh;
    const float* wz = W_hh + (size_t)(j + Hh)     * Hh;
    const float* wn = W_hh + (size_t)(j + 2*Hh)   * Hh;

    float ar[16], az[16], an[16];
#pragma unroll
    for (int b = 0; b < 16; b++) { ar[b] = 0.f; az[b] = 0.f; an[b] = 0.f; }

    for (int i = 0; i < 32; i++) {
        const int k = i*32 + lane;
        const float vr = wr[k];
        const float vz = wz[k];
        const float vn = wn[k];
#pragma unroll
        for (int b = 0; b < 16; b++) {
            const float hv = h_s[b*Hh + k];
            ar[b] = fmaf(vr, hv, ar[b]);
            az[b] = fmaf(vz, hv, az[b]);
            an[b] = fmaf(vn, hv, an[b]);
        }
    }

#pragma unroll
    for (int b = 0; b < 16; b++) {
#pragma unroll
        for (int o = 16; o > 0; o >>= 1) {
            ar[b] += __shfl_xor_sync(0xffffffffu, ar[b], o);
            az[b] += __shfl_xor_sync(0xffffffffu, az[b], o);
            an[b] += __shfl_xor_sync(0xffffffffu, an[b], o);
        }
    }

    if (lane < 16) {
        const int b = lane;
        const float* gi = g_gi + ((size_t)(b*Tt + t)) * G3;
        const float ir  = gi[j];
        const float iz  = gi[j + Hh];
        const float inn = gi[j + 2*Hh];
        const float r = 1.f / (1.f + expf(-(ir + ar[b] + b_hh[j])));
        const float z = 1.f / (1.f + expf(-(iz + az[b] + b_hh[j + Hh])));
        const float n = tanhf(inn + r * (an[b] + b_hh[j + 2*Hh]));
        const float hp = h_s[b*Hh + j];
        g_hs[((size_t)(b*Tt + t))*Hh + j] = (1.f - z)*n + z*hp;
    }
}

// ================= log-softmax =================
__global__ void lse_kernel(const float* __restrict__ logits)
{
    const int row = blockIdx.x;
    const float* x = logits + (size_t)row * Vv;
    float m = -INFINITY, s = 0.f;
    for (int v = threadIdx.x; v < Vv; v += 256) {
        const float xv = x[v];
        if (xv > m) { s = s * expf(m - xv) + 1.f; m = xv; }
        else        { s += expf(xv - m); }
    }
    __shared__ float sm[256], ss[256];
    sm[threadIdx.x] = m; ss[threadIdx.x] = s;
    __syncthreads();
    for (int o = 128; o > 0; o >>= 1) {
        if (threadIdx.x < o) {
            const float m2 = sm[threadIdx.x + o], s2 = ss[threadIdx.x + o];
            const float M_ = fmaxf(sm[threadIdx.x], m2);
            ss[threadIdx.x] = ss[threadIdx.x]*expf(sm[threadIdx.x]-M_) + s2*expf(m2-M_);
            sm[threadIdx.x] = M_;
        }
        __syncthreads();
    }
    if (threadIdx.x == 0) g_lse[row] = sm[0] + logf(ss[0]);
}

__global__ void sub_kernel(float* __restrict__ out)
{
    const size_t i = (size_t)blockIdx.x * blockDim.x + threadIdx.x;
    const size_t n4 = (size_t)Mm * Vv / 4;
    if (i >= n4) return;
    const int row = (int)((i * 4) / Vv);
    const float l = g_lse[row];
    float4 v = ((float4*)out)[i];
    v.x -= l; v.y -= l; v.z -= l; v.w -= l;
    ((float4*)out)[i] = v;
}

__global__ void hidden_copy_kernel(float* __restrict__ out)
{
    const int i = blockIdx.x * blockDim.x + threadIdx.x;
    const int b = i >> 10;
    const int j = i & (Hh - 1);
    out[(size_t)Mm*Vv + i] = g_hs[((size_t)(b*Tt + Tt - 1))*Hh + j];
}

// ============================================================
extern "C" void kernel_launch(void* const* d_in, const int* in_sizes, int n_in,
                              void* d_out, int out_size)
{
    const int*   inputs = (const int*)  d_in[0];
    const float* emb    = (const float*)d_in[1];
    const float* W_ih   = (const float*)d_in[2];
    const float* W_hh   = (const float*)d_in[3];
    const float* b_ih   = (const float*)d_in[4];
    const float* b_hh   = (const float*)d_in[5];
    const float* W1     = (const float*)d_in[6];
    const float* b1     = (const float*)d_in[7];
    const float* W2     = (const float*)d_in[8];
    const float* b2     = (const float*)d_in[9];
    float* out = (float*)d_out;

    float *p_gi, *p_hs, *p_y;
    __nv_bfloat16 *p_W1b, *p_W2b, *p_hsb, *p_yb;
    cudaGetSymbolAddress((void**)&p_gi,  g_gi);
    cudaGetSymbolAddress((void**)&p_hs,  g_hs);
    cudaGetSymbolAddress((void**)&p_y,   g_y);
    cudaGetSymbolAddress((void**)&p_W1b, g_W1b);
    cudaGetSymbolAddress((void**)&p_W2b, g_W2b);
    cudaGetSymbolAddress((void**)&p_hsb, g_hsb);
    cudaGetSymbolAddress((void**)&p_yb,  g_yb);

    cudaFuncSetAttribute(gru_step_kernel,
                         cudaFuncAttributeMaxDynamicSharedMemorySize, Bb*Hh*4);
    cudaFuncSetAttribute(hmma_gemm_kernel,
                         cudaFuncAttributeMaxDynamicSharedMemorySize, HG_SMEM);

    // 0) weight -> bf16 (independent)
    f2bf_kernel<<<(Hh*Hh)/1024, 256>>>(W1, p_W1b, (Hh*Hh)/4);
    f2bf_kernel<<<((size_t)Vv*Hh)/1024, 256>>>(W2, p_W2b, (Vv*Hh)/4);

    // 1) gi = gather(emb) @ W_ih^T + b_ih  (fp32)
    {
        dim3 grid(G3/128, Mm/128);
        sgemm_kernel<<<grid, 256>>>(emb, W_ih, b_ih, p_gi, Mm, G3, Ee, inputs, 0);
    }

    // 2) GRU scan
    for (int t = 0; t < Tt; t++)
        gru_step_kernel<<<128, 256, Bb*Hh*4>>>(W_hh, b_hh, t);

    // 3) hs -> bf16
    f2bf_kernel<<<(Mm*Hh)/1024, 256>>>(p_hs, p_hsb, (Mm*Hh)/4);

    // 4) y = relu(hs @ W1^T + b1)  (HMMA bf16)
    {
        dim3 grid(Hh/128, Mm/128);
        hmma_gemm_kernel<<<grid, 256, HG_SMEM>>>(p_hsb, p_W1b, b1, p_y, Mm, Hh, Hh, 1);
    }

    // 5) y -> bf16
    f2bf_kernel<<<(Mm*Hh)/1024, 256>>>(p_y, p_yb, (Mm*Hh)/4);

    // 6) logits = y @ W2^T + b2  (HMMA bf16)
    {
        dim3 grid(Vv/128, Mm/128);
        hmma_gemm_kernel<<<grid, 256, HG_SMEM>>>(p_yb, p_W2b, b2, out, Mm, Vv, Hh, 0);
    }

    // 7) log_softmax
    lse_kernel<<<Mm, 256>>>(out);
    {
        const size_t n4 = (size_t)Mm * Vv / 4;
        sub_kernel<<<(int)((n4 + 255) / 256), 256>>>(out);
    }

    // 8) hidden
    hidden_copy_kernel<<<(Bb*Hh)/256, 256>>>(out);
}

// round 4
// speedup vs baseline: 2.6094x; 1.3483x over previous
#include <cuda_runtime.h>
#include <cuda_bf16.h>
#include <math.h>
#include <cstdint>

#define Bb 16
#define Tt 256
#define Ee 512
#define Hh 1024
#define Vv 32000
#define G3 3072
#define Mm (Bb*Tt)   // 4096

#define GRU_BLOCKS 128

// ---- scratch ----
__device__ float g_gi[(size_t)Mm*G3];
__device__ float g_hs[(size_t)Mm*Hh];
__device__ float g_y [(size_t)Mm*Hh];
__device__ float g_lse[Mm];
__device__ __nv_bfloat16 g_W1b[(size_t)Hh*Hh];
__device__ __nv_bfloat16 g_W2b[(size_t)Vv*Hh];
__device__ __nv_bfloat16 g_hsb[(size_t)Mm*Hh];
__device__ __nv_bfloat16 g_yb [(size_t)Mm*Hh];
__device__ unsigned g_cnt = 0;
__device__ unsigned g_gen = 0;

__device__ __forceinline__ uint32_t smem_u32(const void* p) {
    uint32_t a;
    asm("{ .reg .u64 t; cvta.to.shared.u64 t, %1; cvt.u32.u64 %0, t; }" : "=r"(a) : "l"(p));
    return a;
}

// ================= fp32 -> bf16 =================
__global__ void f2bf_kernel(const float* __restrict__ x, __nv_bfloat16* __restrict__ o, int n4)
{
    int i = blockIdx.x * blockDim.x + threadIdx.x;
    if (i >= n4) return;
    float4 v = ((const float4*)x)[i];
    __nv_bfloat162* p = (__nv_bfloat162*)o + i * 2;
    p[0] = __floats2bfloat162_rn(v.x, v.y);
    p[1] = __floats2bfloat162_rn(v.z, v.w);
}

// ================= HMMA bf16 GEMM (unchanged from R3) =================
#define HG_STRIDE  40
#define HG_ATILE   (128 * HG_STRIDE * 2)
#define HG_STAGE   (2 * HG_ATILE)
#define HG_SMEM    (2 * HG_STAGE)

__device__ __forceinline__ void ldsm_x4(uint32_t* r, uint32_t addr) {
    asm volatile("ldmatrix.sync.aligned.m8n8.x4.shared.b16 {%0,%1,%2,%3}, [%4];"
                 : "=r"(r[0]), "=r"(r[1]), "=r"(r[2]), "=r"(r[3]) : "r"(addr));
}
__device__ __forceinline__ void mma16816(float* d, const uint32_t* a, uint32_t b0, uint32_t b1) {
    asm volatile("mma.sync.aligned.m16n8k16.row.col.f32.bf16.bf16.f32 "
                 "{%0,%1,%2,%3}, {%4,%5,%6,%7}, {%8,%9}, {%0,%1,%2,%3};"
                 : "+f"(d[0]), "+f"(d[1]), "+f"(d[2]), "+f"(d[3])
                 : "r"(a[0]), "r"(a[1]), "r"(a[2]), "r"(a[3]), "r"(b0), "r"(b1));
}
__device__ __forceinline__ void cp_async16(uint32_t saddr, const void* gaddr) {
    asm volatile("cp.async.cg.shared.global [%0], [%1], 16;" :: "r"(saddr), "l"(gaddr));
}

__global__ void __launch_bounds__(256) hmma_gemm_kernel(
    const __nv_bfloat16* __restrict__ A,
    const __nv_bfloat16* __restrict__ Bm,
    const float* __restrict__ bias,
    float* __restrict__ C,
    int M, int N, int K, int do_relu)
{
    extern __shared__ char smem[];
    const uint32_t sb = smem_u32(smem);
    const int tid  = threadIdx.x;
    const int wid  = tid >> 5;
    const int lane = tid & 31;
    const int bn = blockIdx.x, bm = blockIdx.y;

    const int warp_m = wid & 3;
    const int warp_n = wid >> 2;

    float d[2][8][4];
#pragma unroll
    for (int i = 0; i < 2; i++)
#pragma unroll
        for (int j = 0; j < 8; j++)
#pragma unroll
            for (int q = 0; q < 4; q++) d[i][j][q] = 0.f;

    const int NK = K >> 5;
    const int lmat = lane >> 3;
    const int lrow = lane & 7;

    auto load_stage = [&](int it, int buf) {
        const int kt = it << 5;
        const uint32_t sa = sb + buf * HG_STAGE;
        const uint32_t sbB = sa + HG_ATILE;
#pragma unroll
        for (int s = 0; s < 2; s++) {
            const int idx = tid + s * 256;
            const int row = idx >> 2, c = idx & 3;
            cp_async16(sa + row * (HG_STRIDE*2) + c * 16,
                       A + (size_t)(bm * 128 + row) * K + kt + c * 8);
            cp_async16(sbB + row * (HG_STRIDE*2) + c * 16,
                       Bm + (size_t)(bn * 128 + row) * K + kt + c * 8);
        }
        asm volatile("cp.async.commit_group;");
    };

    load_stage(0, 0);

    for (int it = 0; it < NK; it++) {
        if (it + 1 < NK) {
            load_stage(it + 1, (it + 1) & 1);
            asm volatile("cp.async.wait_group 1;");
        } else {
            asm volatile("cp.async.wait_group 0;");
        }
        __syncthreads();

        const uint32_t sa  = sb + (it & 1) * HG_STAGE;
        const uint32_t sbB = sa + HG_ATILE;

#pragma unroll
        for (int ks = 0; ks < 2; ks++) {
            uint32_t a[2][4];
#pragma unroll
            for (int mt = 0; mt < 2; mt++) {
                const int row = warp_m * 32 + mt * 16 + (lmat & 1) * 8 + lrow;
                const int c   = ks * 2 + (lmat >> 1);
                ldsm_x4(a[mt], sa + row * (HG_STRIDE*2) + c * 16);
            }
            uint32_t b[4][4];
#pragma unroll
            for (int nt = 0; nt < 4; nt++) {
                const int n = warp_n * 64 + nt * 16 + (lmat >> 1) * 8 + lrow;
                const int c = ks * 2 + (lmat & 1);
                ldsm_x4(b[nt], sbB + n * (HG_STRIDE*2) + c * 16);
            }
#pragma unroll
            for (int mt = 0; mt < 2; mt++)
#pragma unroll
                for (int nt = 0; nt < 4; nt++) {
                    mma16816(d[mt][nt*2+0], a[mt], b[nt][0], b[nt][1]);
                    mma16816(d[mt][nt*2+1], a[mt], b[nt][2], b[nt][3]);
                }
        }
        __syncthreads();
    }

#pragma unroll
    for (int mt = 0; mt < 2; mt++) {
        const int row0 = bm * 128 + warp_m * 32 + mt * 16 + (lane >> 2);
#pragma unroll
        for (int nt8 = 0; nt8 < 8; nt8++) {
            const int col = bn * 128 + warp_n * 64 + nt8 * 8 + (lane & 3) * 2;
            const float b0 = bias[col], b1 = bias[col + 1];
            float2 v0, v1;
            v0.x = d[mt][nt8][0] + b0; v0.y = d[mt][nt8][1] + b1;
            v1.x = d[mt][nt8][2] + b0; v1.y = d[mt][nt8][3] + b1;
            if (do_relu) {
                v0.x = fmaxf(v0.x, 0.f); v0.y = fmaxf(v0.y, 0.f);
                v1.x = fmaxf(v1.x, 0.f); v1.y = fmaxf(v1.y, 0.f);
            }
            *(float2*)(C + (size_t)row0 * N + col)       = v0;
            *(float2*)(C + (size_t)(row0 + 8) * N + col) = v1;
        }
    }
}

// ================= fp32 SIMT SGEMM (gi, gathered A) =================
__global__ void sgemm_kernel(const float* __restrict__ A,
                             const float* __restrict__ Bm,
                             const float* __restrict__ bias,
                             float* __restrict__ C,
                             int M, int N, int K,
                             const int* __restrict__ gidx,
                             int do_relu)
{
    __shared__ float As[8][128];
    __shared__ float Bs[8][128];

    const int tid = threadIdx.x;
    const int bn  = blockIdx.x;
    const int bm  = blockIdx.y;

    const int lrow = tid >> 1;
    const int kq   = (tid & 1) * 4;

    const int arow_g = bm * 128 + lrow;
    const float* Ap = gidx ? (A + (size_t)gidx[arow_g] * K)
                           : (A + (size_t)arow_g * K);
    const float* Bp = Bm + (size_t)(bn * 128 + lrow) * K;

    const int tx = tid & 15;
    const int ty = tid >> 4;
    const int m0 = ty * 8;
    const int n0 = tx * 8;

    float acc[8][8];
#pragma unroll
    for (int i = 0; i < 8; i++)
#pragma unroll
        for (int j = 0; j < 8; j++) acc[i][j] = 0.f;

    for (int kt = 0; kt < K; kt += 8) {
        float4 av = *(const float4*)(Ap + kt + kq);
        float4 bv = *(const float4*)(Bp + kt + kq);
        As[kq+0][lrow] = av.x; As[kq+1][lrow] = av.y;
        As[kq+2][lrow] = av.z; As[kq+3][lrow] = av.w;
        Bs[kq+0][lrow] = bv.x; Bs[kq+1][lrow] = bv.y;
        Bs[kq+2][lrow] = bv.z; Bs[kq+3][lrow] = bv.w;
        __syncthreads();

#pragma unroll
        for (int kk = 0; kk < 8; kk++) {
            float4 a0 = *(const float4*)&As[kk][m0];
            float4 a1 = *(const float4*)&As[kk][m0 + 4];
            float4 b0 = *(const float4*)&Bs[kk][n0];
            float4 b1 = *(const float4*)&Bs[kk][n0 + 4];
            float am[8] = {a0.x,a0.y,a0.z,a0.w,a1.x,a1.y,a1.z,a1.w};
            float bb[8] = {b0.x,b0.y,b0.z,b0.w,b1.x,b1.y,b1.z,b1.w};
#pragma unroll
            for (int i = 0; i < 8; i++)
#pragma unroll
                for (int j = 0; j < 8; j++)
                    acc[i][j] = fmaf(am[i], bb[j], acc[i][j]);
        }
        __syncthreads();
    }

    const int ncol0 = bn * 128 + n0;
    float bsv[8];
#pragma unroll
    for (int j = 0; j < 8; j++) bsv[j] = bias[ncol0 + j];

#pragma unroll
    for (int i = 0; i < 8; i++) {
        const int m = bm * 128 + m0 + i;
        float* crow = C + (size_t)m * N + ncol0;
#pragma unroll
        for (int jq = 0; jq < 2; jq++) {
            float4 v;
            v.x = acc[i][jq*4+0] + bsv[jq*4+0];
            v.y = acc[i][jq*4+1] + bsv[jq*4+1];
            v.z = acc[i][jq*4+2] + bsv[jq*4+2];
            v.w = acc[i][jq*4+3] + bsv[jq*4+3];
            if (do_relu) {
                v.x = fmaxf(v.x, 0.f); v.y = fmaxf(v.y, 0.f);
                v.z = fmaxf(v.z, 0.f); v.w = fmaxf(v.w, 0.f);
            }
            *(float4*)(crow + jq*4) = v;
        }
    }
}

// ================= persistent GRU =================
// 128 blocks x 256 thr, 1 block/SM (160KB smem). Block owns j = blk*8 + warp.
// smem: W_s[24][1024] (gates r,z,n x 8 warps) then h_s[16][1024].
__device__ __forceinline__ void grid_sync_gru() {
    __syncthreads();
    if (threadIdx.x == 0) {
        __threadfence();
        unsigned gen = *(volatile unsigned*)&g_gen;
        unsigned old = atomicAdd(&g_cnt, 1);
        if (old == GRU_BLOCKS - 1) {
            g_cnt = 0;
            __threadfence();
            atomicAdd(&g_gen, 1);
        } else {
            while (*(volatile unsigned*)&g_gen == gen) __nanosleep(32);
        }
        __threadfence();
    }
    __syncthreads();
}

__global__ void __launch_bounds__(256) gru_persistent_kernel(
    const float* __restrict__ W_hh,
    const float* __restrict__ b_hh)
{
    extern __shared__ float smf[];
    float* W_s = smf;                 // 24*1024 floats
    float* h_s = smf + 24*1024;       // 16*1024 floats

    const int tid  = threadIdx.x;
    const int w    = tid >> 5;
    const int lane = tid & 31;
    const int blk  = blockIdx.x;
    const int j    = blk * 8 + w;

    // preload W_hh slice: rows (g*1024 + blk*8 + wr), g=0..2, wr=0..7
    for (int idx = tid; idx < 24 * 256; idx += 256) {
        const int r = idx >> 8;          // 0..23
        const int q = idx & 255;         // float4 idx within row
        const int g = r >> 3, wr = r & 7;
        *(float4*)&W_s[r*1024 + q*4] =
            *(const float4*)&W_hh[((size_t)(g*Hh + blk*8 + wr))*Hh + q*4];
    }
    // h_0 = 0
    for (int i = tid; i < Bb*Hh/4; i += 256)
        ((float4*)h_s)[i] = make_float4(0.f,0.f,0.f,0.f);
    __syncthreads();

    const float* wr_s = W_s + (0*8 + w) * 1024;
    const float* wz_s = W_s + (1*8 + w) * 1024;
    const float* wn_s = W_s + (2*8 + w) * 1024;
    const float bhr = b_hh[j], bhz = b_hh[j + Hh], bhn = b_hh[j + 2*Hh];

    for (int t = 0; t < Tt; t++) {
        // prefetch gi for this (j, t) early (lane<16 only uses it)
        float ir = 0.f, iz = 0.f, inn = 0.f;
        if (lane < 16) {
            const float* gi = g_gi + ((size_t)(lane*Tt + t)) * G3;
            ir  = __ldcg(gi + j);
            iz  = __ldcg(gi + j + Hh);
            inn = __ldcg(gi + j + 2*Hh);
        }

        float ar[16], az[16], an[16];
#pragma unroll
        for (int b = 0; b < 16; b++) { ar[b] = 0.f; az[b] = 0.f; an[b] = 0.f; }

        for (int i = 0; i < 32; i++) {
            const int k = i*32 + lane;
            const float vr = wr_s[k];
            const float vz = wz_s[k];
            const float vn = wn_s[k];
#pragma unroll
            for (int b = 0; b < 16; b++) {
                const float hv = h_s[b*Hh + k];
                ar[b] = fmaf(vr, hv, ar[b]);
                az[b] = fmaf(vz, hv, az[b]);
                an[b] = fmaf(vn, hv, an[b]);
            }
        }

#pragma unroll
        for (int b = 0; b < 16; b++) {
#pragma unroll
            for (int o = 16; o > 0; o >>= 1) {
                ar[b] += __shfl_xor_sync(0xffffffffu, ar[b], o);
                az[b] += __shfl_xor_sync(0xffffffffu, az[b], o);
                an[b] += __shfl_xor_sync(0xffffffffu, an[b], o);
            }
        }

        float h_new = 0.f;
        if (lane < 16) {
            const int b = lane;
            const float r = 1.f / (1.f + expf(-(ir + ar[b] + bhr)));
            const float z = 1.f / (1.f + expf(-(iz + az[b] + bhz)));
            const float n = tanhf(inn + r * (an[b] + bhn));
            const float hp = h_s[b*Hh + j];
            h_new = (1.f - z)*n + z*hp;
            g_hs[((size_t)(b*Tt + t))*Hh + j] = h_new;
        }

        grid_sync_gru();

        // update h_s for next step: re-stage full h_t from global (L2)
        if (t + 1 < Tt) {
            for (int i = tid*4; i < Bb*Hh; i += 256*4) {
                const int b = i >> 10;
                const int k = i & (Hh-1);
                const float4 v = __ldcg((const float4*)&g_hs[((size_t)(b*Tt + t))*Hh + k]);
                *(float4*)&h_s[i] = v;
            }
            __syncthreads();
        }
    }
}

// ================= log-softmax =================
__global__ void lse_kernel(const float* __restrict__ logits)
{
    const int row = blockIdx.x;
    const float* x = logits + (size_t)row * Vv;
    float m = -INFINITY, s = 0.f;
    for (int v = threadIdx.x; v < Vv; v += 256) {
        const float xv = x[v];
        if (xv > m) { s = s * expf(m - xv) + 1.f; m = xv; }
        else        { s += expf(xv - m); }
    }
    __shared__ float sm[256], ss[256];
    sm[threadIdx.x] = m; ss[threadIdx.x] = s;
    __syncthreads();
    for (int o = 128; o > 0; o >>= 1) {
        if (threadIdx.x < o) {
            const float m2 = sm[threadIdx.x + o], s2 = ss[threadIdx.x + o];
            const float M_ = fmaxf(sm[threadIdx.x], m2);
            ss[threadIdx.x] = ss[threadIdx.x]*expf(sm[threadIdx.x]-M_) + s2*expf(m2-M_);
            sm[threadIdx.x] = M_;
        }
        __syncthreads();
    }
    if (threadIdx.x == 0) g_lse[row] = sm[0] + logf(ss[0]);
}

__global__ void sub_kernel(float* __restrict__ out)
{
    const size_t i = (size_t)blockIdx.x * blockDim.x + threadIdx.x;
    const size_t n4 = (size_t)Mm * Vv / 4;
    if (i >= n4) return;
    const int row = (int)((i * 4) / Vv);
    const float l = g_lse[row];
    float4 v = ((float4*)out)[i];
    v.x -= l; v.y -= l; v.z -= l; v.w -= l;
    ((float4*)out)[i] = v;
}

__global__ void hidden_copy_kernel(float* __restrict__ out)
{
    const int i = blockIdx.x * blockDim.x + threadIdx.x;
    const int b = i >> 10;
    const int j = i & (Hh - 1);
    out[(size_t)Mm*Vv + i] = g_hs[((size_t)(b*Tt + Tt - 1))*Hh + j];
}

// ============================================================
extern "C" void kernel_launch(void* const* d_in, const int* in_sizes, int n_in,
                              void* d_out, int out_size)
{
    const int*   inputs = (const int*)  d_in[0];
    const float* emb    = (const float*)d_in[1];
    const float* W_ih   = (const float*)d_in[2];
    const float* W_hh   = (const float*)d_in[3];
    const float* b_ih   = (const float*)d_in[4];
    const float* b_hh   = (const float*)d_in[5];
    const float* W1     = (const float*)d_in[6];
    const float* b1     = (const float*)d_in[7];
    const float* W2     = (const float*)d_in[8];
    const float* b2     = (const float*)d_in[9];
    float* out = (float*)d_out;

    float *p_gi, *p_hs, *p_y;
    __nv_bfloat16 *p_W1b, *p_W2b, *p_hsb, *p_yb;
    cudaGetSymbolAddress((void**)&p_gi,  g_gi);
    cudaGetSymbolAddress((void**)&p_hs,  g_hs);
    cudaGetSymbolAddress((void**)&p_y,   g_y);
    cudaGetSymbolAddress((void**)&p_W1b, g_W1b);
    cudaGetSymbolAddress((void**)&p_W2b, g_W2b);
    cudaGetSymbolAddress((void**)&p_hsb, g_hsb);
    cudaGetSymbolAddress((void**)&p_yb,  g_yb);

    const int gru_smem = (24*1024 + 16*1024) * 4;   // 163840 B
    cudaFuncSetAttribute(gru_persistent_kernel,
                         cudaFuncAttributeMaxDynamicSharedMemorySize, gru_smem);
    cudaFuncSetAttribute(hmma_gemm_kernel,
                         cudaFuncAttributeMaxDynamicSharedMemorySize, HG_SMEM);

    // 0) weight -> bf16 (independent)
    f2bf_kernel<<<(Hh*Hh)/1024, 256>>>(W1, p_W1b, (Hh*Hh)/4);
    f2bf_kernel<<<((size_t)Vv*Hh)/1024, 256>>>(W2, p_W2b, (Vv*Hh)/4);

    // 1) gi = gather(emb) @ W_ih^T + b_ih  (fp32)
    {
        dim3 grid(G3/128, Mm/128);
        sgemm_kernel<<<grid, 256>>>(emb, W_ih, b_ih, p_gi, Mm, G3, Ee, inputs, 0);
    }

    // 2) GRU scan — single persistent kernel
    gru_persistent_kernel<<<GRU_BLOCKS, 256, gru_smem>>>(W_hh, b_hh);

    // 3) hs -> bf16
    f2bf_kernel<<<(Mm*Hh)/1024, 256>>>(p_hs, p_hsb, (Mm*Hh)/4);

    // 4) y = relu(hs @ W1^T + b1)  (HMMA bf16)
    {
        dim3 grid(Hh/128, Mm/128);
        hmma_gemm_kernel<<<grid, 256, HG_SMEM>>>(p_hsb, p_W1b, b1, p_y, Mm, Hh, Hh, 1);
    }

    // 5) y -> bf16
    f2bf_kernel<<<(Mm*Hh)/1024, 256>>>(p_y, p_yb, (Mm*Hh)/4);

    // 6) logits = y @ W2^T + b2  (HMMA bf16)
    {
        dim3 grid(Vv/128, Mm/128);
        hmma_gemm_kernel<<<grid, 256, HG_SMEM>>>(p_yb, p_W2b, b2, out, Mm, Vv, Hh, 0);
    }

    // 7) log_softmax
    lse_kernel<<<Mm, 256>>>(out);
    {
        const size_t n4 = (size_t)Mm * Vv / 4;
        sub_kernel<<<(int)((n4 + 255) / 256), 256>>>(out);
    }

    // 8) hidden
    hidden_copy_kernel<<<(Bb*Hh)/256, 256>>>(out);
}